// round 2
// baseline (speedup 1.0000x reference)
#include <cuda_runtime.h>

// DepthwiseStencil3D: x (1,16,128,128,128) fp32 -> out flat channels ch = c*6+k,
// each channel = x[c] shifted by one of 6 unit taps, zero-padded.
// Taps (k): 0 -> w+1, 1 -> w-1, 2 -> h+1, 3 -> h-1, 4 -> d+1, 5 -> d-1.
//
// One thread per float4 along W: 4 vector loads + 2 scalar edge loads,
// 6 float4 stores. HBM-bound; writes (805 MB) dominate.

#define C_ 16
#define D_ 128
#define H_ 128
#define W_ 128
#define HW_ (H_ * W_)          // 16384
#define DHW_ (D_ * HW_)        // 2097152

__global__ void __launch_bounds__(256) stencil6_kernel(
    const float* __restrict__ x, float* __restrict__ out)
{
    // tid enumerates (c, d, h, w4): 16 * 128 * 128 * 32 = 8,388,608 threads
    int tid = blockIdx.x * blockDim.x + threadIdx.x;

    int w4 = tid & 31;            // float4 index along W (W/4 = 32)
    int h  = (tid >> 5) & 127;
    int d  = (tid >> 12) & 127;
    int c  = tid >> 19;           // 0..15

    int w0      = w4 << 2;                       // starting w of this float4
    int spatial = d * HW_ + h * W_ + w0;         // within-channel element offset
    int base    = c * DHW_ + spatial;            // element index into x

    const float4* __restrict__ x4 = reinterpret_cast<const float4*>(x);
    float4* __restrict__ o4 = reinterpret_cast<float4*>(out);

    const float4 zero4 = make_float4(0.f, 0.f, 0.f, 0.f);

    // Center row vector + left/right edge scalars for the w-shift taps.
    float4 v  = x4[base >> 2];
    float  xl = (w0 > 0)      ? x[base - 1] : 0.f;
    float  xr = (w0 + 4 < W_) ? x[base + 4] : 0.f;

    // Neighbor rows/slabs (zero outside the volume == zero padding).
    float4 vhp = (h < H_ - 1) ? x4[(base + W_)  >> 2] : zero4;
    float4 vhm = (h > 0)      ? x4[(base - W_)  >> 2] : zero4;
    float4 vdp = (d < D_ - 1) ? x4[(base + HW_) >> 2] : zero4;
    float4 vdm = (d > 0)      ? x4[(base - HW_) >> 2] : zero4;

    // k=0: x[w+1] -> {v.y, v.z, v.w, xr}
    float4 k0 = make_float4(v.y, v.z, v.w, xr);
    // k=1: x[w-1] -> {xl, v.x, v.y, v.z}
    float4 k1 = make_float4(xl, v.x, v.y, v.z);

    // Output: flat channel ch = c*6 + k. Offset = (c*6 + k)*DHW + spatial.
    int ob4 = ((c * 6) * DHW_ + spatial) >> 2;   // k = 0 slot
    const int kstride4 = DHW_ >> 2;              // float4 stride between taps

    o4[ob4]                = k0;
    o4[ob4 + 1 * kstride4] = k1;
    o4[ob4 + 2 * kstride4] = vhp;
    o4[ob4 + 3 * kstride4] = vhm;
    o4[ob4 + 4 * kstride4] = vdp;
    o4[ob4 + 5 * kstride4] = vdm;
}

extern "C" void kernel_launch(void* const* d_in, const int* in_sizes, int n_in,
                              void* d_out, int out_size)
{
    const float* x = (const float*)d_in[0];
    float* out = (float*)d_out;

    // 16 * 128^3 / 4 = 8,388,608 threads
    const int threads = 256;
    const int total = (C_ * DHW_) / 4;
    const int blocks = total / threads;   // 32768

    stencil6_kernel<<<blocks, threads>>>(x, out);
}

// round 3
// speedup vs baseline: 1.0147x; 1.0147x over previous
#include <cuda_runtime.h>

// DepthwiseStencil3D: x (1,16,128,128,128) fp32 -> out flat channels ch = c*6+k,
// each channel = x[c] shifted by one of 6 unit taps, zero-padded.
// Taps (k): 0 -> w+1, 1 -> w-1, 2 -> h+1, 3 -> h-1, 4 -> d+1, 5 -> d-1.
//
// One thread per float4 along W. A warp spans exactly one W-row (32*4 = 128),
// so the w±1 edge scalars come from warp shuffles instead of extra loads.
// 5 float4 loads + 6 streaming float4 stores per thread. HBM-bound.

#define C_ 16
#define D_ 128
#define H_ 128
#define W_ 128
#define HW_ (H_ * W_)          // 16384
#define DHW_ (D_ * HW_)        // 2097152

__global__ void __launch_bounds__(256, 8) stencil6_kernel(
    const float* __restrict__ x, float* __restrict__ out)
{
    // tid enumerates (c, d, h, w4): 16 * 128 * 128 * 32 = 8,388,608 threads
    int tid = blockIdx.x * blockDim.x + threadIdx.x;

    int w4 = tid & 31;            // float4 index along W == lane id
    int h  = (tid >> 5) & 127;
    int d  = (tid >> 12) & 127;
    int c  = tid >> 19;           // 0..15

    int spatial = d * HW_ + h * W_ + (w4 << 2);  // within-channel element offset
    int base    = c * DHW_ + spatial;            // element index into x

    const float4* __restrict__ x4 = reinterpret_cast<const float4*>(x);
    float4* __restrict__ o4 = reinterpret_cast<float4*>(out);

    const float4 zero4 = make_float4(0.f, 0.f, 0.f, 0.f);

    // Center row vector; w-edge scalars via intra-warp shuffle (warp == W row).
    float4 v  = x4[base >> 2];
    float  xl = __shfl_up_sync(0xffffffffu, v.w, 1);   // x[base-1] from lane-1
    float  xr = __shfl_down_sync(0xffffffffu, v.x, 1); // x[base+4] from lane+1
    if (w4 == 0)  xl = 0.f;    // zero padding at w = -1
    if (w4 == 31) xr = 0.f;    // zero padding at w = 128

    // Neighbor rows/slabs (zero outside the volume == zero padding).
    float4 vhp = (h < H_ - 1) ? x4[(base + W_)  >> 2] : zero4;
    float4 vhm = (h > 0)      ? x4[(base - W_)  >> 2] : zero4;
    float4 vdp = (d < D_ - 1) ? x4[(base + HW_) >> 2] : zero4;
    float4 vdm = (d > 0)      ? x4[(base - HW_) >> 2] : zero4;

    // k=0: x[w+1] -> {v.y, v.z, v.w, xr};  k=1: x[w-1] -> {xl, v.x, v.y, v.z}
    float4 k0 = make_float4(v.y, v.z, v.w, xr);
    float4 k1 = make_float4(xl, v.x, v.y, v.z);

    // Output: flat channel ch = c*6 + k. Offset = (c*6 + k)*DHW + spatial.
    int ob4 = ((c * 6) * DHW_ + spatial) >> 2;   // k = 0 slot
    const int kstride4 = DHW_ >> 2;              // float4 stride between taps

    // Streaming stores: output is write-once; keep L2 for input reuse.
    __stcs(&o4[ob4],                k0);
    __stcs(&o4[ob4 + 1 * kstride4], k1);
    __stcs(&o4[ob4 + 2 * kstride4], vhp);
    __stcs(&o4[ob4 + 3 * kstride4], vhm);
    __stcs(&o4[ob4 + 4 * kstride4], vdp);
    __stcs(&o4[ob4 + 5 * kstride4], vdm);
}

extern "C" void kernel_launch(void* const* d_in, const int* in_sizes, int n_in,
                              void* d_out, int out_size)
{
    const float* x = (const float*)d_in[0];
    float* out = (float*)d_out;

    const int threads = 256;
    const int total = (C_ * DHW_) / 4;     // 8,388,608 threads
    const int blocks = total / threads;    // 32768

    stencil6_kernel<<<blocks, threads>>>(x, out);
}